// round 14
// baseline (speedup 1.0000x reference)
#include <cuda_runtime.h>
#include <cuda_bf16.h>
#include <math.h>
#include <stdint.h>

#define TTOK 8192
#define DM   512
#define QKVN 1536
#define HFF  2048
#define NE   8
#define NSEQ 1024
#define DH   64
#define NL   4
#define SLOTMAX (2*TTOK + NE*128)   /* 17408 */
#define MAXRB   (SLOTMAX/128)       /* 136   */

typedef __nv_bfloat16  bf16;
typedef __nv_bfloat162 bf162;

// ---------------- static device scratch (splits stored 2-wide: [hi|lo]) ----------------
__device__ __align__(128) float g_x[TTOK*DM];
__device__ __align__(128) float g_y[TTOK*DM];
__device__ __align__(128) float g_qkv[(size_t)TTOK*QKVN];
__device__ __align__(128) float g_y2[(size_t)SLOTMAX*DM];
__device__ __align__(128) float g_logits[TTOK*NE];
__device__ __align__(128) bf16  g_yh[(size_t)TTOK*2*DM];
__device__ __align__(128) bf16  g_qh[(size_t)64*NSEQ*2*DH];
__device__ __align__(128) bf16  g_kh[(size_t)64*NSEQ*2*DH];
__device__ __align__(128) bf16  g_vth[(size_t)64*DH*2*NSEQ];
__device__ __align__(128) bf16  g_attnsp[(size_t)TTOK*2*DM];
__device__ __align__(128) bf16  g_hh[(size_t)SLOTMAX*2*HFF];
__device__ __align__(128) bf16  g_qkvwT[(size_t)NL*QKVN*2*DM];
__device__ __align__(128) bf16  g_outwT[(size_t)NL*DM*2*DM];
__device__ __align__(128) bf16  g_e1T[(size_t)NL*NE*HFF*2*DM];
__device__ __align__(128) bf16  g_e2T[(size_t)NL*NE*DM*2*HFF];
__device__ int   g_e0[TTOK], g_e1i[TTOK];
__device__ float g_g0[TTOK], g_g1[TTOK];
__device__ int   g_cnt[NE], g_off[NE], g_cur[NE];
__device__ int   g_map[MAXRB];
__device__ int   g_tok[SLOTMAX];
__device__ int   g_slotA[TTOK], g_slotB[TTOK];

// ---------------- low-level helpers ----------------
__device__ __forceinline__ uint32_t smem_u32(const void* p){
    uint32_t a; asm("{ .reg .u64 t; cvta.to.shared.u64 t, %1; cvt.u32.u64 %0, t; }":"=r"(a):"l"(p)); return a;
}
__device__ __forceinline__ void cpasync16(uint32_t dst, const void* src){
    asm volatile("cp.async.cg.shared.global [%0], [%1], 16;" :: "r"(dst), "l"(src));
}
#define CP_COMMIT() asm volatile("cp.async.commit_group;" ::: "memory")
#define CP_WAIT1()  asm volatile("cp.async.wait_group 1;" ::: "memory")
#define CP_WAIT0()  asm volatile("cp.async.wait_group 0;" ::: "memory")
__device__ __forceinline__ void ldm4(uint32_t* r, uint32_t a){
    asm volatile("ldmatrix.sync.aligned.m8n8.x4.shared.b16 {%0,%1,%2,%3}, [%4];"
        : "=r"(r[0]),"=r"(r[1]),"=r"(r[2]),"=r"(r[3]) : "r"(a));
}
__device__ __forceinline__ void mma16816(float* c, const uint32_t* a, const uint32_t* b){
    asm volatile("mma.sync.aligned.m16n8k16.row.col.f32.bf16.bf16.f32 "
        "{%0,%1,%2,%3}, {%4,%5,%6,%7}, {%8,%9}, {%0,%1,%2,%3};"
        : "+f"(c[0]),"+f"(c[1]),"+f"(c[2]),"+f"(c[3])
        : "r"(a[0]),"r"(a[1]),"r"(a[2]),"r"(a[3]), "r"(b[0]),"r"(b[1]));
}
__device__ __forceinline__ float gelu_f(float x){ return 0.5f*x*(1.f+erff(x*0.70710678118654752f)); }
__device__ __forceinline__ void split2(float v, bf16& hi, bf16& lo){
    hi = __float2bfloat16_rn(v);
    lo = __float2bfloat16_rn(v - __bfloat162float(hi));
}

// ---------------- bf16 mma GEMM core (3-stage cp.async, occ 2) ----------------
// Logical C[128,BN] = A[128, 3*Ko] x Bt[BN, 3*Ko]^T with A segs [hi,lo,hi], B segs [hi,hi,lo],
// storage 2-wide [hi|lo]; chunk remap: ca = c<2ma? c : c-2ma ; cb = c<mb? c : c-mb.
// EPI: 1 fp32 out *scale; 3 fp32 RMW +bias (residual); 4 gelu(+bias)->2-seg bf16 (seg); 5 fp32 out +bias
template<int BN, int EPI>
__device__ __forceinline__ void mma_core(
    const bf16* a0,const bf16* a1,const bf16* a2,const bf16* a3,
    const bf16* b0,const bf16* b1,const bf16* b2,const bf16* b3,
    void* Cv, int ldc, const float* bias, int K, float scale, int seg, int ma, int mb)
{
    extern __shared__ __align__(128) char dsm[];
    constexpr int STAGE = 16384 + BN*128;
    const uint32_t sb = smem_u32(dsm);
    const int tid = threadIdx.x;
    const int lane = tid & 31, wid = tid >> 5;
    const int wm = wid & 3, wn = wid >> 2;
    const bf16* Ar[4] = {a0,a1,a2,a3};
    const bf16* Br[4] = {b0,b1,b2,b3};
    constexpr int NBR = BN/32;
    constexpr int NT  = BN/16;

    float acc[2][NT][4];
    #pragma unroll
    for (int mt=0;mt<2;mt++)
        #pragma unroll
        for (int nt=0;nt<NT;nt++)
            #pragma unroll
            for (int q=0;q<4;q++) acc[mt][nt][q]=0.f;

    const int r8 = tid>>3, cu = tid&7;
    auto load_stage = [&](int st, int kc){
        const int ca = (kc < 2*ma) ? kc : kc - 2*ma;
        const int cb = (kc < mb)   ? kc : kc - mb;
        uint32_t ua = sb + st*STAGE;
        uint32_t ub = ua + 16384;
        #pragma unroll
        for (int i=0;i<4;i++){
            uint32_t ro = r8 + 32*i;
            cpasync16(ua + ro*128 + ((cu ^ (ro&7))<<4), Ar[i] + ca*64);
        }
        #pragma unroll
        for (int i=0;i<NBR;i++){
            uint32_t ro = r8 + 32*i;
            cpasync16(ub + ro*128 + ((cu ^ (ro&7))<<4), Br[i] + cb*64);
        }
    };
    auto compute_stage = [&](int st){
        uint32_t ua = sb + st*STAGE;
        uint32_t ub = ua + 16384;
        #pragma unroll
        for (int ks=0;ks<4;ks++){
            uint32_t a[2][4];
            #pragma unroll
            for (int mt=0;mt<2;mt++){
                uint32_t r = wm*32 + mt*16 + (lane&15);
                uint32_t c = ks*2 + (lane>>4);
                ldm4(a[mt], ua + r*128 + ((c ^ (r&7))<<4));
            }
            uint32_t b[NT][2];
            #pragma unroll
            for (int p=0;p<NT/2;p++){
                uint32_t r = wn*(BN/2) + p*16 + ((lane>>4)<<3) + (lane&7);
                uint32_t c = ks*2 + ((lane>>3)&1);
                uint32_t t[4];
                ldm4(t, ub + r*128 + ((c ^ (r&7))<<4));
                b[2*p][0]=t[0]; b[2*p][1]=t[1]; b[2*p+1][0]=t[2]; b[2*p+1][1]=t[3];
            }
            #pragma unroll
            for (int mt=0;mt<2;mt++)
                #pragma unroll
                for (int nt=0;nt<NT;nt++)
                    mma16816(acc[mt][nt], a[mt], b[nt]);
        }
    };

    const int nk = K >> 6;
    load_stage(0,0); CP_COMMIT();
    load_stage(1,1); CP_COMMIT();
    for (int k0=0;k0<nk;k0++){
        CP_WAIT1();
        __syncthreads();
        if (k0+2 < nk) load_stage((k0+2)%3, k0+2);
        CP_COMMIT();
        compute_stage(k0%3);
    }

    #pragma unroll
    for (int mt=0;mt<2;mt++){
        #pragma unroll
        for (int nt=0;nt<NT;nt++){
            int m0 = wm*32 + mt*16 + (lane>>2);
            int n  = wn*(BN/2) + nt*8 + ((lane&3)<<1);
            #pragma unroll
            for (int h=0;h<2;h++){
                int m = m0 + h*8;
                float v0 = acc[mt][nt][2*h], v1 = acc[mt][nt][2*h+1];
                if (EPI==1){
                    *(float2*)((float*)Cv + (size_t)m*ldc + n) = make_float2(v0*scale, v1*scale);
                } else if (EPI==3){
                    float2 bb = *(const float2*)(bias + n);
                    float* p = (float*)Cv + (size_t)m*ldc + n;
                    float2 o = *(float2*)p;
                    *(float2*)p = make_float2(o.x+v0+bb.x, o.y+v1+bb.y);
                } else if (EPI==4){
                    float2 bb = *(const float2*)(bias + n);
                    float g0 = gelu_f(v0+bb.x), g1 = gelu_f(v1+bb.y);
                    bf16 h0,l0,h1,l1; split2(g0,h0,l0); split2(g1,h1,l1);
                    bf16* p = (bf16*)Cv + (size_t)m*ldc + n;
                    *(bf162*)p         = bf162(h0,h1);
                    *(bf162*)(p + seg) = bf162(l0,l1);
                } else if (EPI==5){
                    float2 bb = *(const float2*)(bias + n);
                    *(float2*)((float*)Cv + (size_t)m*ldc + n) = make_float2(v0+bb.x, v1+bb.y);
                }
            }
        }
    }
}

// ---------------- GEMM wrappers ----------------
template<int EPI>
__global__ void __launch_bounds__(256,2) k_mma(
    const bf16* __restrict__ A, int lda,
    const bf16* __restrict__ Bt, int ldb,
    float* __restrict__ C, int ldc,
    const float* __restrict__ bias, int K, float scale, int ma, int mb)
{
    const int t=threadIdx.x, r=t>>3, co=(t&7)*8;
    const bf16* a[4]; const bf16* b[4];
    #pragma unroll
    for (int i=0;i<4;i++){
        a[i] = A  + (size_t)(blockIdx.y*128 + r + 32*i)*lda + co;
        b[i] = Bt + (size_t)(blockIdx.x*128 + r + 32*i)*ldb + co;
    }
    float* Ct = C + (size_t)blockIdx.y*128*ldc + blockIdx.x*128;
    const float* bi = bias ? bias + blockIdx.x*128 : (const float*)0;
    mma_core<128,EPI>(a[0],a[1],a[2],a[3],b[0],b[1],b[2],b[3],Ct,ldc,bi,K,scale,0,ma,mb);
}

template<int EPI, int GATHER>
__global__ void __launch_bounds__(256,2) k_moe_mma(
    const bf16* __restrict__ Abase, int lda,
    const bf16* __restrict__ BtAll, int ldb,
    void* __restrict__ Cbase, int ldc,
    const float* __restrict__ biasAll, int K, int N, int seg, int ma, int mb)
{
    const int e = g_map[blockIdx.y];
    if (e < 0) return;
    const bf16* Bt = BtAll + (size_t)e*N*(size_t)ldb;
    const float* bias = biasAll + (size_t)e*N + blockIdx.x*128;
    const int t=threadIdx.x, r=t>>3, co=(t&7)*8;
    const bf16* a[4]; const bf16* b[4];
    if (GATHER){
        const int lim = g_off[e] + g_cnt[e];
        #pragma unroll
        for (int i=0;i<4;i++){
            int s = blockIdx.y*128 + r + 32*i;
            int tok = (s < lim) ? g_tok[s] : 0;
            a[i] = Abase + (size_t)tok*lda + co;
        }
    } else {
        #pragma unroll
        for (int i=0;i<4;i++)
            a[i] = Abase + (size_t)(blockIdx.y*128 + r + 32*i)*lda + co;
    }
    #pragma unroll
    for (int i=0;i<4;i++)
        b[i] = Bt + (size_t)(blockIdx.x*128 + r + 32*i)*ldb + co;
    char* Ct;
    if (EPI==4) Ct = (char*)Cbase + ((size_t)blockIdx.y*128*ldc + blockIdx.x*128)*2;
    else        Ct = (char*)Cbase + ((size_t)blockIdx.y*128*ldc + blockIdx.x*128)*4;
    mma_core<128,EPI>(a[0],a[1],a[2],a[3],b[0],b[1],b[2],b[3],(void*)Ct,ldc,bias,K,1.f,seg,ma,mb);
}

// ---------------- fused flash attention (no-max softmax) ----------------
#define FSMEM 99328
__global__ void __launch_bounds__(256,2) k_flash(){
    extern __shared__ __align__(128) char dsm[];
    const uint32_t sb = smem_u32(dsm);
    const uint32_t uQ = sb, uK = sb+32768, uV = sb+49152, uP = sb+65536;
    float* Rs = (float*)(dsm + 98304);
    const int bh = blockIdx.y, q0 = blockIdx.x*128;
    const int bb_ = bh>>3, head = bh&7;
    const int tid = threadIdx.x, lane = tid&31, wid = tid>>5;
    const int wm = wid&3, wn = wid>>2;

    const bf16* Qg = g_qh + ((size_t)bh*NSEQ + q0)*(2*DH);
    const bf16* Kg0 = g_kh + (size_t)bh*NSEQ*(2*DH);
    const bf16* Vg0 = g_vth + (size_t)bh*DH*2*NSEQ;

    auto loadK = [&](int j){
        const bf16* Kg = Kg0 + (size_t)(j*64)*(2*DH);
        #pragma unroll
        for (int i=0;i<2;i++){
            int idx = tid + i*256;
            int row = idx>>3, cu = idx&7;
            uint32_t sw = (uint32_t)((cu ^ (row&7))<<4);
            cpasync16(uK + row*128 + sw, Kg + (size_t)row*(2*DH) + cu*8);
            cpasync16(uK + 8192 + row*128 + sw, Kg + (size_t)row*(2*DH) + 64 + cu*8);
        }
    };
    auto loadV = [&](int j){
        const bf16* Vg = Vg0 + j*64;
        #pragma unroll
        for (int i=0;i<2;i++){
            int idx = tid + i*256;
            int row = idx>>3, cu = idx&7;
            uint32_t sw = (uint32_t)((cu ^ (row&7))<<4);
            cpasync16(uV + row*128 + sw, Vg + (size_t)row*2*NSEQ + cu*8);
            cpasync16(uV + 8192 + row*128 + sw, Vg + (size_t)row*2*NSEQ + NSEQ + cu*8);
        }
    };

    #pragma unroll
    for (int i=0;i<4;i++){
        int idx = tid + i*256;
        int row = idx>>3, cu = idx&7;
        uint32_t sw = (uint32_t)((cu ^ (row&7))<<4);
        cpasync16(uQ + row*128 + sw, Qg + (size_t)row*(2*DH) + cu*8);
        cpasync16(uQ + 16384 + row*128 + sw, Qg + (size_t)row*(2*DH) + 64 + cu*8);
    }
    loadK(0); loadV(0); CP_COMMIT();

    float Oacc[2][4][4];
    #pragma unroll
    for (int mt=0;mt<2;mt++)
        #pragma unroll
        for (int nt=0;nt<4;nt++)
            #pragma unroll
            for (int q=0;q<4;q++) Oacc[mt][nt][q]=0.f;
    float ps[2][2]; ps[0][0]=0.f; ps[0][1]=0.f; ps[1][0]=0.f; ps[1][1]=0.f;

    const int qcs[3]={0,1,0}, kcs[3]={0,0,1};

    for (int j=0;j<16;j++){
        CP_WAIT0();
        __syncthreads();

        float S[2][4][4];
        #pragma unroll
        for (int mt=0;mt<2;mt++)
            #pragma unroll
            for (int nt=0;nt<4;nt++)
                #pragma unroll
                for (int q=0;q<4;q++) S[mt][nt][q]=0.f;
        #pragma unroll
        for (int r3=0;r3<3;r3++){
            uint32_t qb = uQ + qcs[r3]*16384;
            uint32_t kb = uK + kcs[r3]*8192;
            #pragma unroll
            for (int ks=0;ks<4;ks++){
                uint32_t a[2][4];
                #pragma unroll
                for (int mt=0;mt<2;mt++){
                    uint32_t r = wm*32 + mt*16 + (lane&15);
                    uint32_t c = ks*2 + (lane>>4);
                    ldm4(a[mt], qb + r*128 + ((c ^ (r&7))<<4));
                }
                uint32_t b[4][2];
                #pragma unroll
                for (int p=0;p<2;p++){
                    uint32_t r = wn*32 + p*16 + ((lane>>4)<<3) + (lane&7);
                    uint32_t c = ks*2 + ((lane>>3)&1);
                    uint32_t t4[4];
                    ldm4(t4, kb + r*128 + ((c ^ (r&7))<<4));
                    b[2*p][0]=t4[0]; b[2*p][1]=t4[1]; b[2*p+1][0]=t4[2]; b[2*p+1][1]=t4[3];
                }
                #pragma unroll
                for (int mt=0;mt<2;mt++)
                    #pragma unroll
                    for (int nt=0;nt<4;nt++)
                        mma16816(S[mt][nt], a[mt], b[nt]);
            }
        }

        #pragma unroll
        for (int mt=0;mt<2;mt++)
            #pragma unroll
            for (int nt=0;nt<4;nt++)
                #pragma unroll
                for (int hh=0;hh<2;hh++){
                    float p0 = __expf(S[mt][nt][2*hh]   * 0.125f);
                    float p1 = __expf(S[mt][nt][2*hh+1] * 0.125f);
                    ps[mt][hh] += p0 + p1;
                    bf16 h0,l0,h1,l1; split2(p0,h0,l0); split2(p1,h1,l1);
                    int rloc = wm*32 + mt*16 + (lane>>2) + 8*hh;
                    int c = wn*32 + nt*8 + (lane&3)*2;
                    uint32_t off = (uint32_t)rloc*128 + (uint32_t)((((c>>3) ^ (rloc&7))<<4) + (c&7)*2);
                    *(bf162*)(dsm + 65536 + off)         = bf162(h0,h1);
                    *(bf162*)(dsm + 65536 + 16384 + off) = bf162(l0,l1);
                }
        __syncthreads();
        if (j+1<16){ loadK(j+1); CP_COMMIT(); }

        const int pcs[3]={0,1,0}, vcs[3]={0,0,1};
        #pragma unroll
        for (int r3=0;r3<3;r3++){
            uint32_t pb = uP + pcs[r3]*16384;
            uint32_t vb = uV + vcs[r3]*8192;
            #pragma unroll
            for (int ks=0;ks<4;ks++){
                uint32_t a[2][4];
                #pragma unroll
                for (int mt=0;mt<2;mt++){
                    uint32_t r = wm*32 + mt*16 + (lane&15);
                    uint32_t c = ks*2 + (lane>>4);
                    ldm4(a[mt], pb + r*128 + ((c ^ (r&7))<<4));
                }
                uint32_t b[4][2];
                #pragma unroll
                for (int p=0;p<2;p++){
                    uint32_t r = wn*32 + p*16 + ((lane>>4)<<3) + (lane&7);
                    uint32_t c = ks*2 + ((lane>>3)&1);
                    uint32_t t4[4];
                    ldm4(t4, vb + r*128 + ((c ^ (r&7))<<4));
                    b[2*p][0]=t4[0]; b[2*p][1]=t4[1]; b[2*p+1][0]=t4[2]; b[2*p+1][1]=t4[3];
                }
                #pragma unroll
                for (int mt=0;mt<2;mt++)
                    #pragma unroll
                    for (int nt=0;nt<4;nt++)
                        mma16816(Oacc[mt][nt], a[mt], b[nt]);
            }
        }
        __syncthreads();
        if (j+1<16){ loadV(j+1); CP_COMMIT(); }
    }

    #pragma unroll
    for (int mt=0;mt<2;mt++)
        #pragma unroll
        for (int hh=0;hh<2;hh++){
            float s = ps[mt][hh];
            s += __shfl_xor_sync(0xffffffffu, s, 1);
            s += __shfl_xor_sync(0xffffffffu, s, 2);
            int rloc = wm*32 + mt*16 + (lane>>2) + 8*hh;
            if ((lane&3)==0) Rs[rloc*2 + wn] = s;
        }
    __syncthreads();

    #pragma unroll
    for (int mt=0;mt<2;mt++)
        #pragma unroll
        for (int hh=0;hh<2;hh++){
            int rloc = wm*32 + mt*16 + (lane>>2) + 8*hh;
            float inv = 1.0f / (Rs[rloc*2] + Rs[rloc*2+1]);
            int rg = bb_*NSEQ + q0 + rloc;
            #pragma unroll
            for (int nt=0;nt<4;nt++){
                int n = wn*32 + nt*8 + (lane&3)*2;
                float v0 = Oacc[mt][nt][2*hh]*inv, v1 = Oacc[mt][nt][2*hh+1]*inv;
                bf16 h0,l0,h1,l1; split2(v0,h0,l0); split2(v1,h1,l1);
                bf16* p = g_attnsp + (size_t)rg*(2*DM) + head*DH + n;
                *(bf162*)p      = bf162(h0,h1);
                *(bf162*)(p+DM) = bf162(l0,l1);
            }
        }
}

// ---------------- conversions / transposes (2-wide splits) ----------------
__global__ void k_trw3(const float* __restrict__ in, bf16* __restrict__ out, int R, int C){
    __shared__ float tile[32][33];
    const float* I = in + (size_t)blockIdx.z*R*C;
    bf16* O = out + (size_t)blockIdx.z*R*C*2;
    int r0=blockIdx.y*32, c0=blockIdx.x*32;
    int x=threadIdx.x, y=threadIdx.y;
    #pragma unroll
    for (int i=0;i<4;i++) tile[y+8*i][x] = I[(size_t)(r0+y+8*i)*C + c0+x];
    __syncthreads();
    #pragma unroll
    for (int i=0;i<4;i++){
        float v = tile[x][y+8*i];
        bf16 hi, lo; split2(v, hi, lo);
        bf16* p = O + (size_t)(c0+y+8*i)*2*R + r0+x;
        p[0] = hi; p[R] = lo;
    }
}

__global__ void k_cvt_qk(){
    int gid = blockIdx.x*blockDim.x + threadIdx.x;   // TTOK*512
    int t = gid >> 9, c = gid & 511;
    int h = c >> 6, d = c & 63;
    int b = t >> 10, n = t & 1023;
    size_t base = ((size_t)(b*8+h)*NSEQ + n)*(2*DH);
    float qv = g_qkv[(size_t)t*QKVN + c];
    float kv = g_qkv[(size_t)t*QKVN + 512 + c];
    bf16 qh,ql,kh,kl; split2(qv,qh,ql); split2(kv,kh,kl);
    g_qh[base + d] = qh; g_qh[base + 64 + d] = ql;
    g_kh[base + d] = kh; g_kh[base + 64 + d] = kl;
}

__global__ void k_trv3(){
    __shared__ float tile[32][33];
    int bh=blockIdx.z, b=bh>>3, h=bh&7;
    const float* I = g_qkv + (size_t)b*NSEQ*QKVN + 1024 + h*DH;
    bf16* O = g_vth + (size_t)bh*DH*2*NSEQ;
    int n0=blockIdx.y*32, d0=blockIdx.x*32;
    int x=threadIdx.x, y=threadIdx.y;
    #pragma unroll
    for (int i=0;i<4;i++) tile[y+8*i][x] = I[(size_t)(n0+y+8*i)*QKVN + d0+x];
    __syncthreads();
    #pragma unroll
    for (int i=0;i<4;i++){
        float v = tile[x][y+8*i];
        bf16 hi, lo; split2(v, hi, lo);
        bf16* p = O + (size_t)(d0+y+8*i)*2*NSEQ + n0+x;
        p[0] = hi; p[NSEQ] = lo;
    }
}

// ---------------- elementwise / routing ----------------
__global__ void k_copy4(const float4* __restrict__ in, float4* __restrict__ out, int n4){
    int i = blockIdx.x*blockDim.x + threadIdx.x;
    if (i < n4) out[i] = in[i];
}

template<int F32OUT>
__global__ void k_ln_h(const float* __restrict__ in, bf16* __restrict__ outh,
                       float* __restrict__ outf,
                       const float* __restrict__ w, const float* __restrict__ b){
    int t = blockIdx.x, i = threadIdx.x;
    float4 v = ((const float4*)(in + (size_t)t*DM))[i];
    float s  = v.x+v.y+v.z+v.w;
    float ss = v.x*v.x+v.y*v.y+v.z*v.z+v.w*v.w;
    #pragma unroll
    for (int o=16;o;o>>=1){ s += __shfl_xor_sync(0xffffffffu,s,o); ss += __shfl_xor_sync(0xffffffffu,ss,o); }
    __shared__ float sh_s[4], sh_q[4];
    int wid = i>>5, lane = i&31;
    if (lane==0){ sh_s[wid]=s; sh_q[wid]=ss; }
    __syncthreads();
    s  = sh_s[0]+sh_s[1]+sh_s[2]+sh_s[3];
    ss = sh_q[0]+sh_q[1]+sh_q[2]+sh_q[3];
    float mean = s * (1.0f/DM);
    float var  = ss * (1.0f/DM) - mean*mean;
    float inv  = rsqrtf(var + 1e-5f);
    float4 wv = ((const float4*)w)[i];
    float4 bv = ((const float4*)b)[i];
    float4 o;
    o.x=(v.x-mean)*inv*wv.x+bv.x; o.y=(v.y-mean)*inv*wv.y+bv.y;
    o.z=(v.z-mean)*inv*wv.z+bv.z; o.w=(v.w-mean)*inv*wv.w+bv.w;
    bf16* p = outh + (size_t)t*2*DM + 4*i;
    bf16 h0,l0,h1,l1,h2,l2,h3,l3;
    split2(o.x,h0,l0); split2(o.y,h1,l1); split2(o.z,h2,l2); split2(o.w,h3,l3);
    *(bf162*)(p)      = bf162(h0,h1); *(bf162*)(p+2)      = bf162(h2,h3);
    *(bf162*)(p+DM)   = bf162(l0,l1); *(bf162*)(p+DM+2)   = bf162(l2,l3);
    if (F32OUT) ((float4*)(outf + (size_t)t*DM))[i] = o;
}

__global__ void k_ln_f(const float* __restrict__ in, float* __restrict__ out,
                       const float* __restrict__ w, const float* __restrict__ b){
    int t = blockIdx.x, i = threadIdx.x;
    float4 v = ((const float4*)(in + (size_t)t*DM))[i];
    float s  = v.x+v.y+v.z+v.w;
    float ss = v.x*v.x+v.y*v.y+v.z*v.z+v.w*v.w;
    #pragma unroll
    for (int o=16;o;o>>=1){ s += __shfl_xor_sync(0xffffffffu,s,o); ss += __shfl_xor_sync(0xffffffffu,ss,o); }
    __shared__ float sh_s[4], sh_q[4];
    int wid = i>>5, lane = i&31;
    if (lane==0){ sh_s[wid]=s; sh_q[wid]=ss; }
    __syncthreads();
    s  = sh_s[0]+sh_s[1]+sh_s[2]+sh_s[3];
    ss = sh_q[0]+sh_q[1]+sh_q[2]+sh_q[3];
    float mean = s * (1.0f/DM);
    float var  = ss * (1.0f/DM) - mean*mean;
    float inv  = rsqrtf(var + 1e-5f);
    float4 wv = ((const float4*)w)[i];
    float4 bv = ((const float4*)b)[i];
    float4 o;
    o.x=(v.x-mean)*inv*wv.x+bv.x; o.y=(v.y-mean)*inv*wv.y+bv.y;
    o.z=(v.z-mean)*inv*wv.z+bv.z; o.w=(v.w-mean)*inv*wv.w+bv.w;
    ((float4*)(out + (size_t)t*DM))[i] = o;
}

// vectorized gate: thread = (token, 4-expert half); float4 loads only
__global__ void k_gate(const float* __restrict__ wg){
    int gid = blockIdx.x*blockDim.x + threadIdx.x;
    if (gid >= TTOK*2) return;
    int t = gid >> 1, he = gid & 1;
    const float4* xr = (const float4*)(g_y + (size_t)t*DM);
    const float4* wp = (const float4*)wg + he;     // row k -> wp[2*k]
    float a0=0.f, a1=0.f, a2=0.f, a3=0.f;
    #pragma unroll 4
    for (int k4=0;k4<128;k4++){
        float4 xv = xr[k4];
        float4 w0 = wp[2*(4*k4+0)];
        float4 w1 = wp[2*(4*k4+1)];
        float4 w2 = wp[2*(4*k4+2)];
        float4 w3 = wp[2*(4*k4+3)];
        a0 = fmaf(xv.x,w0.x, fmaf(xv.y,w1.x, fmaf(xv.z,w2.x, fmaf(xv.w,w3.x, a0))));
        a1 = fmaf(xv.x,w0.y, fmaf(xv.y,w1.y, fmaf(xv.z,w2.y, fmaf(xv.w,w3.y, a1))));
        a2 = fmaf(xv.x,w0.z, fmaf(xv.y,w1.z, fmaf(xv.z,w2.z, fmaf(xv.w,w3.z, a2))));
        a3 = fmaf(xv.x,w0.w, fmaf(xv.y,w1.w, fmaf(xv.z,w2.w, fmaf(xv.w,w3.w, a3))));
    }
    float4 r; r.x=a0; r.y=a1; r.z=a2; r.w=a3;
    *(float4*)(g_logits + (size_t)t*NE + he*4) = r;
}

__global__ void k_zero_cnt(){ if (threadIdx.x < NE) g_cnt[threadIdx.x] = 0; }

__global__ void k_top2(){
    int t = blockIdx.x*blockDim.x + threadIdx.x;
    if (t >= TTOK) return;
    const float* lr = g_logits + t*NE;
    int i0 = 0; float v0 = lr[0];
    #pragma unroll
    for (int e=1;e<NE;e++){ float v = lr[e]; if (v > v0){ v0=v; i0=e; } }
    int i1 = -1; float v1 = -3.4e38f;
    #pragma unroll
    for (int e=0;e<NE;e++){ if (e==i0) continue; float v = lr[e]; if (v > v1){ v1=v; i1=e; } }
    float e1v = expf(v1 - v0);
    float inv = 1.0f/(1.0f + e1v);
    g_e0[t]=i0; g_e1i[t]=i1;
    g_g0[t]=inv; g_g1[t]=e1v*inv;
    atomicAdd(&g_cnt[i0],1);
    atomicAdd(&g_cnt[i1],1);
}

// merged scan + scatter (single block, 256 thr)
__global__ void k_scan_scatter(){
    if (threadIdx.x == 0){
        int off = 0, rb = 0;
        for (int e=0;e<NE;e++){
            g_off[e] = off; g_cur[e] = off;
            int nb = (g_cnt[e] + 127) >> 7;
            for (int i=0;i<nb;i++) g_map[rb++] = e;
            off += nb*128;
        }
        for (; rb<MAXRB; rb++) g_map[rb] = -1;
    }
    __syncthreads();
    for (int t = threadIdx.x; t < TTOK; t += blockDim.x){
        int p0 = atomicAdd(&g_cur[g_e0[t]], 1);  g_tok[p0]=t; g_slotA[t]=p0;
        int p1 = atomicAdd(&g_cur[g_e1i[t]], 1); g_tok[p1]=t; g_slotB[t]=p1;
    }
}

__global__ void k_combine(){
    int t = blockIdx.x, i = threadIdx.x;
    float gg0 = g_g0[t], gg1 = g_g1[t];
    float4 a = ((const float4*)(g_y2 + (size_t)g_slotA[t]*DM))[i];
    float4 b = ((const float4*)(g_y2 + (size_t)g_slotB[t]*DM))[i];
    float4* xr = (float4*)(g_x + (size_t)t*DM);
    float4 xv = xr[i];
    xv.x += gg0*a.x + gg1*b.x;
    xv.y += gg0*a.y + gg1*b.y;
    xv.z += gg0*a.z + gg1*b.z;
    xv.w += gg0*a.w + gg1*b.w;
    xr[i] = xv;
}

// ---------------- host orchestration ----------------
#define SMEM128 (3*(16384 + 128*128))   /* 98304 */

extern "C" void kernel_launch(void* const* d_in, const int* in_sizes, int n_in,
                              void* d_out, int out_size){
    (void)in_sizes; (void)n_in; (void)out_size;
    const float* x    = (const float*)d_in[0];
    const float* ln1w = (const float*)d_in[1];
    const float* ln1b = (const float*)d_in[2];
    const float* qkvw = (const float*)d_in[3];
    const float* outw = (const float*)d_in[4];
    const float* outb = (const float*)d_in[5];
    const float* ln2w = (const float*)d_in[6];
    const float* ln2b = (const float*)d_in[7];
    const float* wg   = (const float*)d_in[8];
    const float* ew1  = (const float*)d_in[9];
    const float* eb1  = (const float*)d_in[10];
    const float* ew2  = (const float*)d_in[11];
    const float* eb2  = (const float*)d_in[12];
    const float* flnw = (const float*)d_in[13];
    const float* flnb = (const float*)d_in[14];
    float* out = (float*)d_out;

    float *px, *py, *pq, *py2;
    bf16 *pyh, *phh, *pattnsp, *pqkvT, *poutT, *pe1T, *pe2T;
    cudaGetSymbolAddress((void**)&px,   g_x);
    cudaGetSymbolAddress((void**)&py,   g_y);
    cudaGetSymbolAddress((void**)&pq,   g_qkv);
    cudaGetSymbolAddress((void**)&py2,  g_y2);
    cudaGetSymbolAddress((void**)&pyh,  g_yh);
    cudaGetSymbolAddress((void**)&phh,  g_hh);
    cudaGetSymbolAddress((void**)&pattnsp, g_attnsp);
    cudaGetSymbolAddress((void**)&pqkvT,g_qkvwT);
    cudaGetSymbolAddress((void**)&poutT,g_outwT);
    cudaGetSymbolAddress((void**)&pe1T, g_e1T);
    cudaGetSymbolAddress((void**)&pe2T, g_e2T);

    cudaFuncSetAttribute(k_mma<1>, cudaFuncAttributeMaxDynamicSharedMemorySize, SMEM128);
    cudaFuncSetAttribute(k_mma<3>, cudaFuncAttributeMaxDynamicSharedMemorySize, SMEM128);
    cudaFuncSetAttribute(k_flash, cudaFuncAttributeMaxDynamicSharedMemorySize, FSMEM);
    cudaFuncSetAttribute(k_moe_mma<4,1>, cudaFuncAttributeMaxDynamicSharedMemorySize, SMEM128);
    cudaFuncSetAttribute(k_moe_mma<5,0>, cudaFuncAttributeMaxDynamicSharedMemorySize, SMEM128);

    {   int n4 = TTOK*DM/4;
        k_copy4<<<(n4+255)/256, 256>>>((const float4*)x, (float4*)px, n4); }

    // weight transpose + 2-wide bf16 split
    k_trw3<<<dim3(QKVN/32, DM/32, NL), dim3(32,8)>>>(qkvw, pqkvT, DM, QKVN);
    k_trw3<<<dim3(DM/32,   DM/32, NL), dim3(32,8)>>>(outw, poutT, DM, DM);
    k_trw3<<<dim3(HFF/32,  DM/32, NL*NE), dim3(32,8)>>>(ew1, pe1T, DM, HFF);
    k_trw3<<<dim3(DM/32,  HFF/32, NL*NE), dim3(32,8)>>>(ew2, pe2T, HFF, DM);

    for (int l=0;l<NL;l++){
        // ---- attention ----
        k_ln_h<0><<<TTOK,128>>>(px, pyh, (float*)0, ln1w + l*DM, ln1b + l*DM);
        k_mma<1><<<dim3(QKVN/128, TTOK/128), 256, SMEM128>>>(
            pyh, 2*DM, pqkvT + (size_t)l*QKVN*2*DM, 2*DM, pq, QKVN,
            (const float*)0, 3*DM, 1.f, DM/64, DM/64);
        k_cvt_qk<<<(TTOK*512)/256, 256>>>();
        k_trv3<<<dim3(2, NSEQ/32, 64), dim3(32,8)>>>();
        k_flash<<<dim3(NSEQ/128, 64), 256, FSMEM>>>();
        k_mma<3><<<dim3(DM/128, TTOK/128), 256, SMEM128>>>(
            pattnsp, 2*DM, poutT + (size_t)l*DM*2*DM, 2*DM, px, DM,
            outb + l*DM, 3*DM, 1.f, DM/64, DM/64);
        // ---- MoE ----
        k_ln_h<1><<<TTOK,128>>>(px, pyh, py, ln2w + l*DM, ln2b + l*DM);
        k_zero_cnt<<<1,32>>>();
        k_gate<<<(TTOK*2)/256, 256>>>(wg + (size_t)l*DM*NE);
        k_top2<<<TTOK/256, 256>>>();
        k_scan_scatter<<<1,256>>>();
        k_moe_mma<4,1><<<dim3(HFF/128, MAXRB), 256, SMEM128>>>(
            pyh, 2*DM, pe1T + (size_t)l*NE*HFF*2*DM, 2*DM, phh, 2*HFF,
            eb1 + (size_t)l*NE*HFF, 3*DM, HFF, HFF, DM/64, DM/64);
        k_moe_mma<5,0><<<dim3(DM/128, MAXRB), 256, SMEM128>>>(
            phh, 2*HFF, pe2T + (size_t)l*NE*DM*2*HFF, 2*HFF, py2, DM,
            eb2 + (size_t)l*NE*DM, 3*HFF, DM, 0, HFF/64, HFF/64);
        k_combine<<<TTOK,128>>>();
    }

    k_ln_f<<<TTOK,128>>>(px, out, flnw, flnb);
}

// round 15
// speedup vs baseline: 1.0623x; 1.0623x over previous
#include <cuda_runtime.h>
#include <cuda_bf16.h>
#include <math.h>
#include <stdint.h>

#define TTOK 8192
#define DM   512
#define QKVN 1536
#define HFF  2048
#define NE   8
#define NSEQ 1024
#define DH   64
#define NL   4
#define SLOTMAX (2*TTOK + NE*128)   /* 17408 */
#define MAXRB   (SLOTMAX/128)       /* 136   */

typedef __nv_bfloat16  bf16;
typedef __nv_bfloat162 bf162;

// ---------------- static device scratch (splits stored 2-wide: [hi|lo]) ----------------
__device__ __align__(128) float g_x[TTOK*DM];
__device__ __align__(128) float g_y[TTOK*DM];
__device__ __align__(128) float g_qkv[(size_t)TTOK*QKVN];
__device__ __align__(128) float g_y2[(size_t)SLOTMAX*DM];
__device__ __align__(128) float g_logits[TTOK*NE];
__device__ __align__(128) bf16  g_yh[(size_t)TTOK*2*DM];
__device__ __align__(128) bf16  g_qh[(size_t)64*NSEQ*2*DH];
__device__ __align__(128) bf16  g_kh[(size_t)64*NSEQ*2*DH];
__device__ __align__(128) bf16  g_vth[(size_t)64*DH*2*NSEQ];
__device__ __align__(128) bf16  g_attnsp[(size_t)TTOK*2*DM];
__device__ __align__(128) bf16  g_hh[(size_t)SLOTMAX*2*HFF];
__device__ __align__(128) bf16  g_qkvwT[(size_t)NL*QKVN*2*DM];
__device__ __align__(128) bf16  g_outwT[(size_t)NL*DM*2*DM];
__device__ __align__(128) bf16  g_e1T[(size_t)NL*NE*HFF*2*DM];
__device__ __align__(128) bf16  g_e2T[(size_t)NL*NE*DM*2*HFF];
__device__ int   g_e0[TTOK], g_e1i[TTOK];
__device__ float g_g0[TTOK], g_g1[TTOK];
__device__ int   g_cnt[NE], g_off[NE], g_cur[NE];
__device__ int   g_map[MAXRB];
__device__ int   g_tok[SLOTMAX];
__device__ int   g_slotA[TTOK], g_slotB[TTOK];

// ---------------- low-level helpers ----------------
__device__ __forceinline__ uint32_t smem_u32(const void* p){
    uint32_t a; asm("{ .reg .u64 t; cvta.to.shared.u64 t, %1; cvt.u32.u64 %0, t; }":"=r"(a):"l"(p)); return a;
}
__device__ __forceinline__ void cpasync16(uint32_t dst, const void* src){
    asm volatile("cp.async.cg.shared.global [%0], [%1], 16;" :: "r"(dst), "l"(src));
}
#define CP_COMMIT() asm volatile("cp.async.commit_group;" ::: "memory")
#define CP_WAIT1()  asm volatile("cp.async.wait_group 1;" ::: "memory")
#define CP_WAIT0()  asm volatile("cp.async.wait_group 0;" ::: "memory")
__device__ __forceinline__ void ldm4(uint32_t* r, uint32_t a){
    asm volatile("ldmatrix.sync.aligned.m8n8.x4.shared.b16 {%0,%1,%2,%3}, [%4];"
        : "=r"(r[0]),"=r"(r[1]),"=r"(r[2]),"=r"(r[3]) : "r"(a));
}
__device__ __forceinline__ void mma16816(float* c, const uint32_t* a, const uint32_t* b){
    asm volatile("mma.sync.aligned.m16n8k16.row.col.f32.bf16.bf16.f32 "
        "{%0,%1,%2,%3}, {%4,%5,%6,%7}, {%8,%9}, {%0,%1,%2,%3};"
        : "+f"(c[0]),"+f"(c[1]),"+f"(c[2]),"+f"(c[3])
        : "r"(a[0]),"r"(a[1]),"r"(a[2]),"r"(a[3]), "r"(b[0]),"r"(b[1]));
}
__device__ __forceinline__ float gelu_f(float x){ return 0.5f*x*(1.f+erff(x*0.70710678118654752f)); }
__device__ __forceinline__ void split2(float v, bf16& hi, bf16& lo){
    hi = __float2bfloat16_rn(v);
    lo = __float2bfloat16_rn(v - __bfloat162float(hi));
}

// ---------------- bf16 mma GEMM core (3-stage cp.async, occ 2) ----------------
// Logical C[128,BN] = A[128, 3*Ko] x Bt[BN, 3*Ko]^T with A segs [hi,lo,hi], B segs [hi,hi,lo],
// storage 2-wide [hi|lo]; chunk remap: ca = c<2ma? c : c-2ma ; cb = c<mb? c : c-mb.
// EPI: 1 fp32 out *scale; 3 fp32 RMW +bias (residual); 4 gelu(+bias)->2-seg bf16 (seg); 5 fp32 out +bias
template<int BN, int EPI>
__device__ __forceinline__ void mma_core(
    const bf16* a0,const bf16* a1,const bf16* a2,const bf16* a3,
    const bf16* b0,const bf16* b1,const bf16* b2,const bf16* b3,
    void* Cv, int ldc, const float* bias, int K, float scale, int seg, int ma, int mb)
{
    extern __shared__ __align__(128) char dsm[];
    constexpr int STAGE = 16384 + BN*128;
    const uint32_t sb = smem_u32(dsm);
    const int tid = threadIdx.x;
    const int lane = tid & 31, wid = tid >> 5;
    const int wm = wid & 3, wn = wid >> 2;
    const bf16* Ar[4] = {a0,a1,a2,a3};
    const bf16* Br[4] = {b0,b1,b2,b3};
    constexpr int NBR = BN/32;
    constexpr int NT  = BN/16;

    float acc[2][NT][4];
    #pragma unroll
    for (int mt=0;mt<2;mt++)
        #pragma unroll
        for (int nt=0;nt<NT;nt++)
            #pragma unroll
            for (int q=0;q<4;q++) acc[mt][nt][q]=0.f;

    const int r8 = tid>>3, cu = tid&7;
    auto load_stage = [&](int st, int kc){
        const int ca = (kc < 2*ma) ? kc : kc - 2*ma;
        const int cb = (kc < mb)   ? kc : kc - mb;
        uint32_t ua = sb + st*STAGE;
        uint32_t ub = ua + 16384;
        #pragma unroll
        for (int i=0;i<4;i++){
            uint32_t ro = r8 + 32*i;
            cpasync16(ua + ro*128 + ((cu ^ (ro&7))<<4), Ar[i] + ca*64);
        }
        #pragma unroll
        for (int i=0;i<NBR;i++){
            uint32_t ro = r8 + 32*i;
            cpasync16(ub + ro*128 + ((cu ^ (ro&7))<<4), Br[i] + cb*64);
        }
    };
    auto compute_stage = [&](int st){
        uint32_t ua = sb + st*STAGE;
        uint32_t ub = ua + 16384;
        #pragma unroll
        for (int ks=0;ks<4;ks++){
            uint32_t a[2][4];
            #pragma unroll
            for (int mt=0;mt<2;mt++){
                uint32_t r = wm*32 + mt*16 + (lane&15);
                uint32_t c = ks*2 + (lane>>4);
                ldm4(a[mt], ua + r*128 + ((c ^ (r&7))<<4));
            }
            uint32_t b[NT][2];
            #pragma unroll
            for (int p=0;p<NT/2;p++){
                uint32_t r = wn*(BN/2) + p*16 + ((lane>>4)<<3) + (lane&7);
                uint32_t c = ks*2 + ((lane>>3)&1);
                uint32_t t[4];
                ldm4(t, ub + r*128 + ((c ^ (r&7))<<4));
                b[2*p][0]=t[0]; b[2*p][1]=t[1]; b[2*p+1][0]=t[2]; b[2*p+1][1]=t[3];
            }
            #pragma unroll
            for (int mt=0;mt<2;mt++)
                #pragma unroll
                for (int nt=0;nt<NT;nt++)
                    mma16816(acc[mt][nt], a[mt], b[nt]);
        }
    };

    const int nk = K >> 6;
    load_stage(0,0); CP_COMMIT();
    load_stage(1,1); CP_COMMIT();
    for (int k0=0;k0<nk;k0++){
        CP_WAIT1();
        __syncthreads();
        if (k0+2 < nk) load_stage((k0+2)%3, k0+2);
        CP_COMMIT();
        compute_stage(k0%3);
    }

    #pragma unroll
    for (int mt=0;mt<2;mt++){
        #pragma unroll
        for (int nt=0;nt<NT;nt++){
            int m0 = wm*32 + mt*16 + (lane>>2);
            int n  = wn*(BN/2) + nt*8 + ((lane&3)<<1);
            #pragma unroll
            for (int h=0;h<2;h++){
                int m = m0 + h*8;
                float v0 = acc[mt][nt][2*h], v1 = acc[mt][nt][2*h+1];
                if (EPI==1){
                    *(float2*)((float*)Cv + (size_t)m*ldc + n) = make_float2(v0*scale, v1*scale);
                } else if (EPI==3){
                    float2 bb = *(const float2*)(bias + n);
                    float* p = (float*)Cv + (size_t)m*ldc + n;
                    float2 o = *(float2*)p;
                    *(float2*)p = make_float2(o.x+v0+bb.x, o.y+v1+bb.y);
                } else if (EPI==4){
                    float2 bb = *(const float2*)(bias + n);
                    float g0 = gelu_f(v0+bb.x), g1 = gelu_f(v1+bb.y);
                    bf16 h0,l0,h1,l1; split2(g0,h0,l0); split2(g1,h1,l1);
                    bf16* p = (bf16*)Cv + (size_t)m*ldc + n;
                    *(bf162*)p         = bf162(h0,h1);
                    *(bf162*)(p + seg) = bf162(l0,l1);
                } else if (EPI==5){
                    float2 bb = *(const float2*)(bias + n);
                    *(float2*)((float*)Cv + (size_t)m*ldc + n) = make_float2(v0+bb.x, v1+bb.y);
                }
            }
        }
    }
}

// ---------------- GEMM wrappers ----------------
template<int EPI>
__global__ void __launch_bounds__(256,2) k_mma(
    const bf16* __restrict__ A, int lda,
    const bf16* __restrict__ Bt, int ldb,
    float* __restrict__ C, int ldc,
    const float* __restrict__ bias, int K, float scale, int ma, int mb)
{
    const int t=threadIdx.x, r=t>>3, co=(t&7)*8;
    const bf16* a[4]; const bf16* b[4];
    #pragma unroll
    for (int i=0;i<4;i++){
        a[i] = A  + (size_t)(blockIdx.y*128 + r + 32*i)*lda + co;
        b[i] = Bt + (size_t)(blockIdx.x*128 + r + 32*i)*ldb + co;
    }
    float* Ct = C + (size_t)blockIdx.y*128*ldc + blockIdx.x*128;
    const float* bi = bias ? bias + blockIdx.x*128 : (const float*)0;
    mma_core<128,EPI>(a[0],a[1],a[2],a[3],b[0],b[1],b[2],b[3],Ct,ldc,bi,K,scale,0,ma,mb);
}

template<int EPI, int GATHER>
__global__ void __launch_bounds__(256,2) k_moe_mma(
    const bf16* __restrict__ Abase, int lda,
    const bf16* __restrict__ BtAll, int ldb,
    void* __restrict__ Cbase, int ldc,
    const float* __restrict__ biasAll, int K, int N, int seg, int ma, int mb)
{
    const int e = g_map[blockIdx.y];
    if (e < 0) return;
    const bf16* Bt = BtAll + (size_t)e*N*(size_t)ldb;
    const float* bias = biasAll + (size_t)e*N + blockIdx.x*128;
    const int t=threadIdx.x, r=t>>3, co=(t&7)*8;
    const bf16* a[4]; const bf16* b[4];
    if (GATHER){
        const int lim = g_off[e] + g_cnt[e];
        #pragma unroll
        for (int i=0;i<4;i++){
            int s = blockIdx.y*128 + r + 32*i;
            int tok = (s < lim) ? g_tok[s] : 0;
            a[i] = Abase + (size_t)tok*lda + co;
        }
    } else {
        #pragma unroll
        for (int i=0;i<4;i++)
            a[i] = Abase + (size_t)(blockIdx.y*128 + r + 32*i)*lda + co;
    }
    #pragma unroll
    for (int i=0;i<4;i++)
        b[i] = Bt + (size_t)(blockIdx.x*128 + r + 32*i)*ldb + co;
    char* Ct;
    if (EPI==4) Ct = (char*)Cbase + ((size_t)blockIdx.y*128*ldc + blockIdx.x*128)*2;
    else        Ct = (char*)Cbase + ((size_t)blockIdx.y*128*ldc + blockIdx.x*128)*4;
    mma_core<128,EPI>(a[0],a[1],a[2],a[3],b[0],b[1],b[2],b[3],(void*)Ct,ldc,bias,K,1.f,seg,ma,mb);
}

// ---------------- fused flash attention (no-max softmax) ----------------
#define FSMEM 99328
__global__ void __launch_bounds__(256,2) k_flash(){
    extern __shared__ __align__(128) char dsm[];
    const uint32_t sb = smem_u32(dsm);
    const uint32_t uQ = sb, uK = sb+32768, uV = sb+49152, uP = sb+65536;
    float* Rs = (float*)(dsm + 98304);
    const int bh = blockIdx.y, q0 = blockIdx.x*128;
    const int bb_ = bh>>3, head = bh&7;
    const int tid = threadIdx.x, lane = tid&31, wid = tid>>5;
    const int wm = wid&3, wn = wid>>2;

    const bf16* Qg = g_qh + ((size_t)bh*NSEQ + q0)*(2*DH);
    const bf16* Kg0 = g_kh + (size_t)bh*NSEQ*(2*DH);
    const bf16* Vg0 = g_vth + (size_t)bh*DH*2*NSEQ;

    auto loadK = [&](int j){
        const bf16* Kg = Kg0 + (size_t)(j*64)*(2*DH);
        #pragma unroll
        for (int i=0;i<2;i++){
            int idx = tid + i*256;
            int row = idx>>3, cu = idx&7;
            uint32_t sw = (uint32_t)((cu ^ (row&7))<<4);
            cpasync16(uK + row*128 + sw, Kg + (size_t)row*(2*DH) + cu*8);
            cpasync16(uK + 8192 + row*128 + sw, Kg + (size_t)row*(2*DH) + 64 + cu*8);
        }
    };
    auto loadV = [&](int j){
        const bf16* Vg = Vg0 + j*64;
        #pragma unroll
        for (int i=0;i<2;i++){
            int idx = tid + i*256;
            int row = idx>>3, cu = idx&7;
            uint32_t sw = (uint32_t)((cu ^ (row&7))<<4);
            cpasync16(uV + row*128 + sw, Vg + (size_t)row*2*NSEQ + cu*8);
            cpasync16(uV + 8192 + row*128 + sw, Vg + (size_t)row*2*NSEQ + NSEQ + cu*8);
        }
    };

    #pragma unroll
    for (int i=0;i<4;i++){
        int idx = tid + i*256;
        int row = idx>>3, cu = idx&7;
        uint32_t sw = (uint32_t)((cu ^ (row&7))<<4);
        cpasync16(uQ + row*128 + sw, Qg + (size_t)row*(2*DH) + cu*8);
        cpasync16(uQ + 16384 + row*128 + sw, Qg + (size_t)row*(2*DH) + 64 + cu*8);
    }
    loadK(0); loadV(0); CP_COMMIT();

    float Oacc[2][4][4];
    #pragma unroll
    for (int mt=0;mt<2;mt++)
        #pragma unroll
        for (int nt=0;nt<4;nt++)
            #pragma unroll
            for (int q=0;q<4;q++) Oacc[mt][nt][q]=0.f;
    float ps[2][2]; ps[0][0]=0.f; ps[0][1]=0.f; ps[1][0]=0.f; ps[1][1]=0.f;

    const int qcs[3]={0,1,0}, kcs[3]={0,0,1};

    for (int j=0;j<16;j++){
        CP_WAIT0();
        __syncthreads();

        float S[2][4][4];
        #pragma unroll
        for (int mt=0;mt<2;mt++)
            #pragma unroll
            for (int nt=0;nt<4;nt++)
                #pragma unroll
                for (int q=0;q<4;q++) S[mt][nt][q]=0.f;
        #pragma unroll
        for (int r3=0;r3<3;r3++){
            uint32_t qb = uQ + qcs[r3]*16384;
            uint32_t kb = uK + kcs[r3]*8192;
            #pragma unroll
            for (int ks=0;ks<4;ks++){
                uint32_t a[2][4];
                #pragma unroll
                for (int mt=0;mt<2;mt++){
                    uint32_t r = wm*32 + mt*16 + (lane&15);
                    uint32_t c = ks*2 + (lane>>4);
                    ldm4(a[mt], qb + r*128 + ((c ^ (r&7))<<4));
                }
                uint32_t b[4][2];
                #pragma unroll
                for (int p=0;p<2;p++){
                    uint32_t r = wn*32 + p*16 + ((lane>>4)<<3) + (lane&7);
                    uint32_t c = ks*2 + ((lane>>3)&1);
                    uint32_t t4[4];
                    ldm4(t4, kb + r*128 + ((c ^ (r&7))<<4));
                    b[2*p][0]=t4[0]; b[2*p][1]=t4[1]; b[2*p+1][0]=t4[2]; b[2*p+1][1]=t4[3];
                }
                #pragma unroll
                for (int mt=0;mt<2;mt++)
                    #pragma unroll
                    for (int nt=0;nt<4;nt++)
                        mma16816(S[mt][nt], a[mt], b[nt]);
            }
        }

        #pragma unroll
        for (int mt=0;mt<2;mt++)
            #pragma unroll
            for (int nt=0;nt<4;nt++)
                #pragma unroll
                for (int hh=0;hh<2;hh++){
                    float p0 = __expf(S[mt][nt][2*hh]   * 0.125f);
                    float p1 = __expf(S[mt][nt][2*hh+1] * 0.125f);
                    ps[mt][hh] += p0 + p1;
                    bf16 h0,l0,h1,l1; split2(p0,h0,l0); split2(p1,h1,l1);
                    int rloc = wm*32 + mt*16 + (lane>>2) + 8*hh;
                    int c = wn*32 + nt*8 + (lane&3)*2;
                    uint32_t off = (uint32_t)rloc*128 + (uint32_t)((((c>>3) ^ (rloc&7))<<4) + (c&7)*2);
                    *(bf162*)(dsm + 65536 + off)         = bf162(h0,h1);
                    *(bf162*)(dsm + 65536 + 16384 + off) = bf162(l0,l1);
                }
        __syncthreads();
        if (j+1<16){ loadK(j+1); CP_COMMIT(); }

        const int pcs[3]={0,1,0}, vcs[3]={0,0,1};
        #pragma unroll
        for (int r3=0;r3<3;r3++){
            uint32_t pb = uP + pcs[r3]*16384;
            uint32_t vb = uV + vcs[r3]*8192;
            #pragma unroll
            for (int ks=0;ks<4;ks++){
                uint32_t a[2][4];
                #pragma unroll
                for (int mt=0;mt<2;mt++){
                    uint32_t r = wm*32 + mt*16 + (lane&15);
                    uint32_t c = ks*2 + (lane>>4);
                    ldm4(a[mt], pb + r*128 + ((c ^ (r&7))<<4));
                }
                uint32_t b[4][2];
                #pragma unroll
                for (int p=0;p<2;p++){
                    uint32_t r = wn*32 + p*16 + ((lane>>4)<<3) + (lane&7);
                    uint32_t c = ks*2 + ((lane>>3)&1);
                    uint32_t t4[4];
                    ldm4(t4, vb + r*128 + ((c ^ (r&7))<<4));
                    b[2*p][0]=t4[0]; b[2*p][1]=t4[1]; b[2*p+1][0]=t4[2]; b[2*p+1][1]=t4[3];
                }
                #pragma unroll
                for (int mt=0;mt<2;mt++)
                    #pragma unroll
                    for (int nt=0;nt<4;nt++)
                        mma16816(Oacc[mt][nt], a[mt], b[nt]);
            }
        }
        __syncthreads();
        if (j+1<16){ loadV(j+1); CP_COMMIT(); }
    }

    #pragma unroll
    for (int mt=0;mt<2;mt++)
        #pragma unroll
        for (int hh=0;hh<2;hh++){
            float s = ps[mt][hh];
            s += __shfl_xor_sync(0xffffffffu, s, 1);
            s += __shfl_xor_sync(0xffffffffu, s, 2);
            int rloc = wm*32 + mt*16 + (lane>>2) + 8*hh;
            if ((lane&3)==0) Rs[rloc*2 + wn] = s;
        }
    __syncthreads();

    #pragma unroll
    for (int mt=0;mt<2;mt++)
        #pragma unroll
        for (int hh=0;hh<2;hh++){
            int rloc = wm*32 + mt*16 + (lane>>2) + 8*hh;
            float inv = 1.0f / (Rs[rloc*2] + Rs[rloc*2+1]);
            int rg = bb_*NSEQ + q0 + rloc;
            #pragma unroll
            for (int nt=0;nt<4;nt++){
                int n = wn*32 + nt*8 + (lane&3)*2;
                float v0 = Oacc[mt][nt][2*hh]*inv, v1 = Oacc[mt][nt][2*hh+1]*inv;
                bf16 h0,l0,h1,l1; split2(v0,h0,l0); split2(v1,h1,l1);
                bf16* p = g_attnsp + (size_t)rg*(2*DM) + head*DH + n;
                *(bf162*)p      = bf162(h0,h1);
                *(bf162*)(p+DM) = bf162(l0,l1);
            }
        }
}

// ---------------- conversions / transposes (2-wide splits) ----------------
__global__ void k_trw3(const float* __restrict__ in, bf16* __restrict__ out, int R, int C){
    __shared__ float tile[32][33];
    const float* I = in + (size_t)blockIdx.z*R*C;
    bf16* O = out + (size_t)blockIdx.z*R*C*2;
    int r0=blockIdx.y*32, c0=blockIdx.x*32;
    int x=threadIdx.x, y=threadIdx.y;
    #pragma unroll
    for (int i=0;i<4;i++) tile[y+8*i][x] = I[(size_t)(r0+y+8*i)*C + c0+x];
    __syncthreads();
    #pragma unroll
    for (int i=0;i<4;i++){
        float v = tile[x][y+8*i];
        bf16 hi, lo; split2(v, hi, lo);
        bf16* p = O + (size_t)(c0+y+8*i)*2*R + r0+x;
        p[0] = hi; p[R] = lo;
    }
}

// merged: qkv fp32 -> Q/K 2-wide splits (first 16384 blocks) + V transpose split (next 4096)
#define CVT_BLKS 16384
#define TRV_BLKS 4096
__global__ void k_cvt_all(){
    __shared__ float tile[32][33];
    int bid = blockIdx.x;
    if (bid < CVT_BLKS){
        int gid = bid*256 + threadIdx.x;   // TTOK*512
        int t = gid >> 9, c = gid & 511;
        int h = c >> 6, d = c & 63;
        int b = t >> 10, n = t & 1023;
        size_t base = ((size_t)(b*8+h)*NSEQ + n)*(2*DH);
        float qv = g_qkv[(size_t)t*QKVN + c];
        float kv = g_qkv[(size_t)t*QKVN + 512 + c];
        bf16 qh,ql,kh,kl; split2(qv,qh,ql); split2(kv,kh,kl);
        g_qh[base + d] = qh; g_qh[base + 64 + d] = ql;
        g_kh[base + d] = kh; g_kh[base + 64 + d] = kl;
    } else {
        int rb = bid - CVT_BLKS;
        int xx = rb & 1;            // d-tile
        int yy = (rb >> 1) & 31;    // n-tile
        int bh = rb >> 6;           // 0..63
        int b = bh>>3, h = bh&7;
        int x = threadIdx.x & 31, y = threadIdx.x >> 5;   // (32,8)
        const float* I = g_qkv + (size_t)b*NSEQ*QKVN + 1024 + h*DH;
        bf16* O = g_vth + (size_t)bh*DH*2*NSEQ;
        int n0 = yy*32, d0 = xx*32;
        #pragma unroll
        for (int i=0;i<4;i++) tile[y+8*i][x] = I[(size_t)(n0+y+8*i)*QKVN + d0+x];
        __syncthreads();
        #pragma unroll
        for (int i=0;i<4;i++){
            float v = tile[x][y+8*i];
            bf16 hi, lo; split2(v, hi, lo);
            bf16* p = O + (size_t)(d0+y+8*i)*2*NSEQ + n0+x;
            p[0] = hi; p[NSEQ] = lo;
        }
    }
}

// ---------------- elementwise / routing ----------------
__global__ void k_copy4(const float4* __restrict__ in, float4* __restrict__ out, int n4){
    int i = blockIdx.x*blockDim.x + threadIdx.x;
    if (i < n4) out[i] = in[i];
}

template<int F32OUT>
__global__ void k_ln_h(const float* __restrict__ in, bf16* __restrict__ outh,
                       float* __restrict__ outf,
                       const float* __restrict__ w, const float* __restrict__ b){
    int t = blockIdx.x, i = threadIdx.x;
    if (F32OUT && t==0 && i<NE) g_cnt[i]=0;   // fold zero_cnt (runs before k_top2 atomics)
    float4 v = ((const float4*)(in + (size_t)t*DM))[i];
    float s  = v.x+v.y+v.z+v.w;
    float ss = v.x*v.x+v.y*v.y+v.z*v.z+v.w*v.w;
    #pragma unroll
    for (int o=16;o;o>>=1){ s += __shfl_xor_sync(0xffffffffu,s,o); ss += __shfl_xor_sync(0xffffffffu,ss,o); }
    __shared__ float sh_s[4], sh_q[4];
    int wid = i>>5, lane = i&31;
    if (lane==0){ sh_s[wid]=s; sh_q[wid]=ss; }
    __syncthreads();
    s  = sh_s[0]+sh_s[1]+sh_s[2]+sh_s[3];
    ss = sh_q[0]+sh_q[1]+sh_q[2]+sh_q[3];
    float mean = s * (1.0f/DM);
    float var  = ss * (1.0f/DM) - mean*mean;
    float inv  = rsqrtf(var + 1e-5f);
    float4 wv = ((const float4*)w)[i];
    float4 bv = ((const float4*)b)[i];
    float4 o;
    o.x=(v.x-mean)*inv*wv.x+bv.x; o.y=(v.y-mean)*inv*wv.y+bv.y;
    o.z=(v.z-mean)*inv*wv.z+bv.z; o.w=(v.w-mean)*inv*wv.w+bv.w;
    bf16* p = outh + (size_t)t*2*DM + 4*i;
    bf16 h0,l0,h1,l1,h2,l2,h3,l3;
    split2(o.x,h0,l0); split2(o.y,h1,l1); split2(o.z,h2,l2); split2(o.w,h3,l3);
    *(bf162*)(p)      = bf162(h0,h1); *(bf162*)(p+2)      = bf162(h2,h3);
    *(bf162*)(p+DM)   = bf162(l0,l1); *(bf162*)(p+DM+2)   = bf162(l2,l3);
    if (F32OUT) ((float4*)(outf + (size_t)t*DM))[i] = o;
}

__global__ void k_ln_f(const float* __restrict__ in, float* __restrict__ out,
                       const float* __restrict__ w, const float* __restrict__ b){
    int t = blockIdx.x, i = threadIdx.x;
    float4 v = ((const float4*)(in + (size_t)t*DM))[i];
    float s  = v.x+v.y+v.z+v.w;
    float ss = v.x*v.x+v.y*v.y+v.z*v.z+v.w*v.w;
    #pragma unroll
    for (int o=16;o;o>>=1){ s += __shfl_xor_sync(0xffffffffu,s,o); ss += __shfl_xor_sync(0xffffffffu,ss,o); }
    __shared__ float sh_s[4], sh_q[4];
    int wid = i>>5, lane = i&31;
    if (lane==0){ sh_s[wid]=s; sh_q[wid]=ss; }
    __syncthreads();
    s  = sh_s[0]+sh_s[1]+sh_s[2]+sh_s[3];
    ss = sh_q[0]+sh_q[1]+sh_q[2]+sh_q[3];
    float mean = s * (1.0f/DM);
    float var  = ss * (1.0f/DM) - mean*mean;
    float inv  = rsqrtf(var + 1e-5f);
    float4 wv = ((const float4*)w)[i];
    float4 bv = ((const float4*)b)[i];
    float4 o;
    o.x=(v.x-mean)*inv*wv.x+bv.x; o.y=(v.y-mean)*inv*wv.y+bv.y;
    o.z=(v.z-mean)*inv*wv.z+bv.z; o.w=(v.w-mean)*inv*wv.w+bv.w;
    ((float4*)(out + (size_t)t*DM))[i] = o;
}

__global__ void k_gate(const float* __restrict__ wg){
    int gid = blockIdx.x*blockDim.x + threadIdx.x;
    if (gid >= TTOK*NE) return;
    int t = gid>>3, e = gid&7;
    const float* xr = g_y + (size_t)t*DM;
    float s = 0.f;
    #pragma unroll 8
    for (int k=0;k<DM;k++) s = fmaf(xr[k], wg[k*NE+e], s);
    g_logits[t*NE+e] = s;
}

__global__ void k_top2(){
    int t = blockIdx.x*blockDim.x + threadIdx.x;
    if (t >= TTOK) return;
    const float* lr = g_logits + t*NE;
    int i0 = 0; float v0 = lr[0];
    #pragma unroll
    for (int e=1;e<NE;e++){ float v = lr[e]; if (v > v0){ v0=v; i0=e; } }
    int i1 = -1; float v1 = -3.4e38f;
    #pragma unroll
    for (int e=0;e<NE;e++){ if (e==i0) continue; float v = lr[e]; if (v > v1){ v1=v; i1=e; } }
    float e1v = expf(v1 - v0);
    float inv = 1.0f/(1.0f + e1v);
    g_e0[t]=i0; g_e1i[t]=i1;
    g_g0[t]=inv; g_g1[t]=e1v*inv;
    atomicAdd(&g_cnt[i0],1);
    atomicAdd(&g_cnt[i1],1);
}

__global__ void k_scan(){
    int off = 0, rb = 0;
    for (int e=0;e<NE;e++){
        g_off[e] = off; g_cur[e] = off;
        int nb = (g_cnt[e] + 127) >> 7;
        for (int i=0;i<nb;i++) g_map[rb++] = e;
        off += nb*128;
    }
    for (; rb<MAXRB; rb++) g_map[rb] = -1;
}

__global__ void k_scatter(){
    int t = blockIdx.x*blockDim.x + threadIdx.x;
    if (t >= TTOK) return;
    int p0 = atomicAdd(&g_cur[g_e0[t]], 1);  g_tok[p0]=t; g_slotA[t]=p0;
    int p1 = atomicAdd(&g_cur[g_e1i[t]], 1); g_tok[p1]=t; g_slotB[t]=p1;
}

__global__ void k_combine(){
    int t = blockIdx.x, i = threadIdx.x;
    float gg0 = g_g0[t], gg1 = g_g1[t];
    float4 a = ((const float4*)(g_y2 + (size_t)g_slotA[t]*DM))[i];
    float4 b = ((const float4*)(g_y2 + (size_t)g_slotB[t]*DM))[i];
    float4* xr = (float4*)(g_x + (size_t)t*DM);
    float4 xv = xr[i];
    xv.x += gg0*a.x + gg1*b.x;
    xv.y += gg0*a.y + gg1*b.y;
    xv.z += gg0*a.z + gg1*b.z;
    xv.w += gg0*a.w + gg1*b.w;
    xr[i] = xv;
}

// ---------------- host orchestration ----------------
#define SMEM128 (3*(16384 + 128*128))   /* 98304 */

extern "C" void kernel_launch(void* const* d_in, const int* in_sizes, int n_in,
                              void* d_out, int out_size){
    (void)in_sizes; (void)n_in; (void)out_size;
    const float* x    = (const float*)d_in[0];
    const float* ln1w = (const float*)d_in[1];
    const float* ln1b = (const float*)d_in[2];
    const float* qkvw = (const float*)d_in[3];
    const float* outw = (const float*)d_in[4];
    const float* outb = (const float*)d_in[5];
    const float* ln2w = (const float*)d_in[6];
    const float* ln2b = (const float*)d_in[7];
    const float* wg   = (const float*)d_in[8];
    const float* ew1  = (const float*)d_in[9];
    const float* eb1  = (const float*)d_in[10];
    const float* ew2  = (const float*)d_in[11];
    const float* eb2  = (const float*)d_in[12];
    const float* flnw = (const float*)d_in[13];
    const float* flnb = (const float*)d_in[14];
    float* out = (float*)d_out;

    float *px, *py, *pq, *py2;
    bf16 *pyh, *phh, *pattnsp, *pqkvT, *poutT, *pe1T, *pe2T;
    cudaGetSymbolAddress((void**)&px,   g_x);
    cudaGetSymbolAddress((void**)&py,   g_y);
    cudaGetSymbolAddress((void**)&pq,   g_qkv);
    cudaGetSymbolAddress((void**)&py2,  g_y2);
    cudaGetSymbolAddress((void**)&pyh,  g_yh);
    cudaGetSymbolAddress((void**)&phh,  g_hh);
    cudaGetSymbolAddress((void**)&pattnsp, g_attnsp);
    cudaGetSymbolAddress((void**)&pqkvT,g_qkvwT);
    cudaGetSymbolAddress((void**)&poutT,g_outwT);
    cudaGetSymbolAddress((void**)&pe1T, g_e1T);
    cudaGetSymbolAddress((void**)&pe2T, g_e2T);

    cudaFuncSetAttribute(k_mma<1>, cudaFuncAttributeMaxDynamicSharedMemorySize, SMEM128);
    cudaFuncSetAttribute(k_mma<3>, cudaFuncAttributeMaxDynamicSharedMemorySize, SMEM128);
    cudaFuncSetAttribute(k_flash, cudaFuncAttributeMaxDynamicSharedMemorySize, FSMEM);
    cudaFuncSetAttribute(k_moe_mma<4,1>, cudaFuncAttributeMaxDynamicSharedMemorySize, SMEM128);
    cudaFuncSetAttribute(k_moe_mma<5,0>, cudaFuncAttributeMaxDynamicSharedMemorySize, SMEM128);

    {   int n4 = TTOK*DM/4;
        k_copy4<<<(n4+255)/256, 256>>>((const float4*)x, (float4*)px, n4); }

    // weight transpose + 2-wide bf16 split
    k_trw3<<<dim3(QKVN/32, DM/32, NL), dim3(32,8)>>>(qkvw, pqkvT, DM, QKVN);
    k_trw3<<<dim3(DM/32,   DM/32, NL), dim3(32,8)>>>(outw, poutT, DM, DM);
    k_trw3<<<dim3(HFF/32,  DM/32, NL*NE), dim3(32,8)>>>(ew1, pe1T, DM, HFF);
    k_trw3<<<dim3(DM/32,  HFF/32, NL*NE), dim3(32,8)>>>(ew2, pe2T, HFF, DM);

    for (int l=0;l<NL;l++){
        // ---- attention ----
        k_ln_h<0><<<TTOK,128>>>(px, pyh, (float*)0, ln1w + l*DM, ln1b + l*DM);
        k_mma<1><<<dim3(QKVN/128, TTOK/128), 256, SMEM128>>>(
            pyh, 2*DM, pqkvT + (size_t)l*QKVN*2*DM, 2*DM, pq, QKVN,
            (const float*)0, 3*DM, 1.f, DM/64, DM/64);
        k_cvt_all<<<CVT_BLKS + TRV_BLKS, 256>>>();
        k_flash<<<dim3(NSEQ/128, 64), 256, FSMEM>>>();
        k_mma<3><<<dim3(DM/128, TTOK/128), 256, SMEM128>>>(
            pattnsp, 2*DM, poutT + (size_t)l*DM*2*DM, 2*DM, px, DM,
            outb + l*DM, 3*DM, 1.f, DM/64, DM/64);
        // ---- MoE ----
        k_ln_h<1><<<TTOK,128>>>(px, pyh, py, ln2w + l*DM, ln2b + l*DM);
        k_gate<<<(TTOK*NE)/256, 256>>>(wg + (size_t)l*DM*NE);
        k_top2<<<TTOK/256, 256>>>();
        k_scan<<<1,1>>>();
        k_scatter<<<TTOK/256, 256>>>();
        k_moe_mma<4,1><<<dim3(HFF/128, MAXRB), 256, SMEM128>>>(
            pyh, 2*DM, pe1T + (size_t)l*NE*HFF*2*DM, 2*DM, phh, 2*HFF,
            eb1 + (size_t)l*NE*HFF, 3*DM, HFF, HFF, DM/64, DM/64);
        k_moe_mma<5,0><<<dim3(DM/128, MAXRB), 256, SMEM128>>>(
            phh, 2*HFF, pe2T + (size_t)l*NE*DM*2*HFF, 2*HFF, py2, DM,
            eb2 + (size_t)l*NE*DM, 3*HFF, DM, 0, HFF/64, HFF/64);
        k_combine<<<TTOK,128>>>();
    }

    k_ln_f<<<TTOK,128>>>(px, out, flnw, flnb);
}